// round 3
// baseline (speedup 1.0000x reference)
#include <cuda_runtime.h>
#include <cuda_bf16.h>

#define N_NODES 50000
#define N_EDGES 800000
#define FIN 96

// ---------------- scratch (device globals; no allocation allowed) ----------
__device__ int   g_deg[N_NODES];
__device__ int   g_off[N_NODES + 1];
__device__ int   g_cur[N_NODES];
__device__ int   g_bsum[64];
__device__ int   g_esrc[N_EDGES];
__device__ float g_mean[(size_t)N_NODES * FIN];
__device__ float g_h1[(size_t)N_NODES * FIN];
__device__ float g_h2[(size_t)N_NODES * FIN];

__device__ __forceinline__ int clampN(int v) {
    return v < 0 ? 0 : (v >= N_NODES ? N_NODES - 1 : v);
}

// buffer selector resolved in device code (no host-side symbol addressing)
__device__ __forceinline__ const float* src_ptr(int sel, const float* ext) {
    return sel == 1 ? g_h1 : (sel == 2 ? g_h2 : ext);
}
__device__ __forceinline__ float* dst_ptr(int sel, float* ext) {
    return sel == 1 ? g_h1 : (sel == 2 ? g_h2 : ext);
}

// ---------------- CSR build -------------------------------------------------
__global__ void k_zero_deg() {
    int i = blockIdx.x * blockDim.x + threadIdx.x;
    if (i < N_NODES) g_deg[i] = 0;
}

// edge_index is int32 (JAX x64 disabled): row 0 = src, row 1 = dst
__global__ void k_count(const int* __restrict__ ei) {
    int e = blockIdx.x * blockDim.x + threadIdx.x;
    if (e < N_EDGES) {
        int d = clampN(ei[N_EDGES + e]);
        atomicAdd(&g_deg[d], 1);
    }
}

// two-level exclusive scan of g_deg -> g_off
__global__ void k_scan1() {
    __shared__ int s[1024];
    int i = blockIdx.x * 1024 + threadIdx.x;
    int v = (i < N_NODES) ? g_deg[i] : 0;
    s[threadIdx.x] = v;
    __syncthreads();
    for (int d = 1; d < 1024; d <<= 1) {
        int t = (threadIdx.x >= d) ? s[threadIdx.x - d] : 0;
        __syncthreads();
        s[threadIdx.x] += t;
        __syncthreads();
    }
    if (i < N_NODES) g_off[i] = s[threadIdx.x] - v;   // exclusive within block
    if (threadIdx.x == 1023) g_bsum[blockIdx.x] = s[1023];
}

__global__ void k_scan2(int nblk) {
    if (threadIdx.x == 0 && blockIdx.x == 0) {
        int acc = 0;
        for (int b = 0; b < nblk; b++) { int t = g_bsum[b]; g_bsum[b] = acc; acc += t; }
    }
}

__global__ void k_scan3() {
    int i = blockIdx.x * 1024 + threadIdx.x;
    if (i < N_NODES) {
        int o = g_off[i] + g_bsum[blockIdx.x];
        g_off[i] = o;
        g_cur[i] = o;
    }
    if (i == 0) g_off[N_NODES] = N_EDGES;
}

__global__ void k_fill(const int* __restrict__ ei) {
    int e = blockIdx.x * blockDim.x + threadIdx.x;
    if (e < N_EDGES) {
        int s = clampN(ei[e]);
        int d = clampN(ei[N_EDGES + e]);
        int p = atomicAdd(&g_cur[d], 1);
        if (p >= 0 && p < N_EDGES) g_esrc[p] = s;
    }
}

// ---------------- mean aggregation: one warp per node (FIN = 96) ------------
// SRC: 0 = external x (param), 1 = g_h1, 2 = g_h2. Writes g_mean.
template <int SRC>
__global__ void k_agg(const float* __restrict__ ext) {
    const float* hin = src_ptr(SRC, ext);
    int w    = (blockIdx.x * blockDim.x + threadIdx.x) >> 5;
    int lane = threadIdx.x & 31;
    if (w >= N_NODES) return;
    int beg = g_off[w], end = g_off[w + 1];
    float a0 = 0.f, a1 = 0.f, a2 = 0.f;
    int e = beg;
    for (; e + 1 < end; e += 2) {
        const float* r0 = hin + (size_t)g_esrc[e] * FIN;
        const float* r1 = hin + (size_t)g_esrc[e + 1] * FIN;
        float x0 = r0[lane], x1 = r0[lane + 32], x2 = r0[lane + 64];
        float y0 = r1[lane], y1 = r1[lane + 32], y2 = r1[lane + 64];
        a0 += x0 + y0; a1 += x1 + y1; a2 += x2 + y2;
    }
    if (e < end) {
        const float* r0 = hin + (size_t)g_esrc[e] * FIN;
        a0 += r0[lane]; a1 += r0[lane + 32]; a2 += r0[lane + 64];
    }
    int deg = end - beg;
    float inv = 1.0f / (float)(deg > 0 ? deg : 1);
    float* o = g_mean + (size_t)w * FIN;
    o[lane] = a0 * inv; o[lane + 32] = a1 * inv; o[lane + 64] = a2 * inv;
}

// ---------------- fused dual-GEMM + bias + ReLU ------------------------------
// out[i][j] = relu( sum_k mean[i][k]*Wl[k][j] + hin[i][k]*Wr[k][j] + b[j] )
template <int FOUT, int SRC, int DST>
__global__ void __launch_bounds__(128) k_gemm(
    const float* __restrict__ ext_in,
    const float* __restrict__ Wl, const float* __restrict__ Wr,
    const float* __restrict__ bias, float* __restrict__ ext_out)
{
    const float* hin = src_ptr(SRC, ext_in);
    float* out = dst_ptr(DST, ext_out);

    constexpr int TN = 16;          // nodes per block
    constexpr int KC = 32;          // k chunk
    constexpr int JT = FOUT / 3;    // threads along j (32 or 16)
    constexpr int NG = 128 / JT;    // node groups (4 or 8)
    constexpr int NR = TN / NG;     // nodes per thread (4 or 2)

    __shared__ float sWl[KC][FOUT];
    __shared__ float sWr[KC][FOUT];
    __shared__ float sM[TN][KC];
    __shared__ float sH[TN][KC];

    int tid   = threadIdx.x;
    int j0    = tid % JT;
    int ig    = tid / JT;
    int node0 = blockIdx.x * TN;

    float acc[NR][3];
    #pragma unroll
    for (int r = 0; r < NR; r++) { acc[r][0] = 0.f; acc[r][1] = 0.f; acc[r][2] = 0.f; }

    for (int kc = 0; kc < FIN; kc += KC) {
        __syncthreads();
        #pragma unroll
        for (int idx = tid; idx < KC * FOUT; idx += 128) {
            int kk = idx / FOUT, jj = idx % FOUT;
            sWl[kk][jj] = Wl[(kc + kk) * FOUT + jj];
            sWr[kk][jj] = Wr[(kc + kk) * FOUT + jj];
        }
        #pragma unroll
        for (int idx = tid; idx < TN * KC; idx += 128) {
            int ii = idx / KC, kk = idx % KC;
            size_t base = (size_t)(node0 + ii) * FIN + kc + kk;
            sM[ii][kk] = g_mean[base];
            sH[ii][kk] = hin[base];
        }
        __syncthreads();

        #pragma unroll
        for (int k = 0; k < KC; k++) {
            float wl0 = sWl[k][j0], wl1 = sWl[k][j0 + JT], wl2 = sWl[k][j0 + 2 * JT];
            float wr0 = sWr[k][j0], wr1 = sWr[k][j0 + JT], wr2 = sWr[k][j0 + 2 * JT];
            #pragma unroll
            for (int r = 0; r < NR; r++) {
                float m  = sM[ig * NR + r][k];
                float hh = sH[ig * NR + r][k];
                acc[r][0] = fmaf(m, wl0, fmaf(hh, wr0, acc[r][0]));
                acc[r][1] = fmaf(m, wl1, fmaf(hh, wr1, acc[r][1]));
                acc[r][2] = fmaf(m, wl2, fmaf(hh, wr2, acc[r][2]));
            }
        }
    }

    float b0 = bias[j0], b1 = bias[j0 + JT], b2 = bias[j0 + 2 * JT];
    #pragma unroll
    for (int r = 0; r < NR; r++) {
        size_t node = (size_t)node0 + ig * NR + r;
        float* o = out + node * FOUT;
        o[j0]          = fmaxf(acc[r][0] + b0, 0.f);
        o[j0 + JT]     = fmaxf(acc[r][1] + b1, 0.f);
        o[j0 + 2 * JT] = fmaxf(acc[r][2] + b2, 0.f);
    }
}

// ---------------- launch ------------------------------------------------------
extern "C" void kernel_launch(void* const* d_in, const int* in_sizes, int n_in,
                              void* d_out, int out_size)
{
    const float* x   = (const float*)d_in[0];
    const int*   ei  = (const int*)d_in[1];     // int32: JAX x64 disabled
    const float* Wl0 = (const float*)d_in[2];
    const float* Wr0 = (const float*)d_in[3];
    const float* b0  = (const float*)d_in[4];
    const float* Wl1 = (const float*)d_in[5];
    const float* Wr1 = (const float*)d_in[6];
    const float* b1  = (const float*)d_in[7];
    const float* Wl2 = (const float*)d_in[8];
    const float* Wr2 = (const float*)d_in[9];
    const float* b2  = (const float*)d_in[10];
    float*       out = (float*)d_out;

    const int nScanBlk = (N_NODES + 1023) / 1024;   // 49
    const int nEdgeBlk = (N_EDGES + 255) / 256;     // 3125

    // CSR build
    k_zero_deg<<<(N_NODES + 255) / 256, 256>>>();
    k_count<<<nEdgeBlk, 256>>>(ei);
    k_scan1<<<nScanBlk, 1024>>>();
    k_scan2<<<1, 32>>>(nScanBlk);
    k_scan3<<<nScanBlk, 1024>>>();
    k_fill<<<nEdgeBlk, 256>>>(ei);

    const int aggBlk  = (N_NODES + 7) / 8;   // 8 warps/block, warp per node
    const int gemmBlk = N_NODES / 16;        // 3125

    // layer 0: x -> g_h1
    k_agg<0><<<aggBlk, 256>>>(x);
    k_gemm<96, 0, 1><<<gemmBlk, 128>>>(x, Wl0, Wr0, b0, nullptr);
    // layer 1: g_h1 -> g_h2
    k_agg<1><<<aggBlk, 256>>>(nullptr);
    k_gemm<96, 1, 2><<<gemmBlk, 128>>>(nullptr, Wl1, Wr1, b1, nullptr);
    // layer 2: g_h2 -> out (FOUT=48)
    k_agg<2><<<aggBlk, 256>>>(nullptr);
    k_gemm<48, 2, 0><<<gemmBlk, 128>>>(nullptr, Wl2, Wr2, b2, out);
}

// round 4
// speedup vs baseline: 1.1557x; 1.1557x over previous
#include <cuda_runtime.h>
#include <cuda_bf16.h>

#define N_NODES 50000
#define N_EDGES 800000
#define FIN 96

typedef unsigned long long ull;

// ---------------- scratch (device globals; no allocation allowed) ----------
__device__ int   g_deg[N_NODES];
__device__ int   g_off[N_NODES + 1];
__device__ int   g_cur[N_NODES];
__device__ int   g_bsum[64];
__device__ int   g_esrc[N_EDGES];
__device__ float g_mean[(size_t)N_NODES * FIN];
__device__ float g_h1[(size_t)N_NODES * FIN];
__device__ float g_h2[(size_t)N_NODES * FIN];

__device__ __forceinline__ int clampN(int v) {
    return v < 0 ? 0 : (v >= N_NODES ? N_NODES - 1 : v);
}
__device__ __forceinline__ const float* src_ptr(int sel, const float* ext) {
    return sel == 1 ? g_h1 : (sel == 2 ? g_h2 : ext);
}
__device__ __forceinline__ float* dst_ptr(int sel, float* ext) {
    return sel == 1 ? g_h1 : (sel == 2 ? g_h2 : ext);
}

// ---- packed f32x2 helpers (FFMA2: PTX-only on sm_103a) ---------------------
__device__ __forceinline__ ull pack2(float x, float y) {
    ull r;
    asm("mov.b64 %0, {%1, %2};" : "=l"(r) : "f"(x), "f"(y));
    return r;
}
__device__ __forceinline__ ull fma2(ull a, ull b, ull c) {
    ull d;
    asm("fma.rn.f32x2 %0, %1, %2, %3;" : "=l"(d) : "l"(a), "l"(b), "l"(c));
    return d;
}
__device__ __forceinline__ float2 unpack2(ull v) {
    float2 f;
    asm("mov.b64 {%0, %1}, %2;" : "=f"(f.x), "=f"(f.y) : "l"(v));
    return f;
}

// ---------------- CSR build -------------------------------------------------
__global__ void k_zero_deg() {
    int i = blockIdx.x * blockDim.x + threadIdx.x;
    if (i < N_NODES) g_deg[i] = 0;
}

__global__ void k_count(const int* __restrict__ ei) {
    int e = blockIdx.x * blockDim.x + threadIdx.x;
    if (e < N_EDGES) {
        int d = clampN(ei[N_EDGES + e]);
        atomicAdd(&g_deg[d], 1);
    }
}

__global__ void k_scan1() {
    __shared__ int s[1024];
    int i = blockIdx.x * 1024 + threadIdx.x;
    int v = (i < N_NODES) ? g_deg[i] : 0;
    s[threadIdx.x] = v;
    __syncthreads();
    for (int d = 1; d < 1024; d <<= 1) {
        int t = (threadIdx.x >= d) ? s[threadIdx.x - d] : 0;
        __syncthreads();
        s[threadIdx.x] += t;
        __syncthreads();
    }
    if (i < N_NODES) g_off[i] = s[threadIdx.x] - v;   // exclusive within block
    if (threadIdx.x == 1023) g_bsum[blockIdx.x] = s[1023];
}

// scan of block sums folded in: parallel load + tiny serial smem sum
__global__ void k_scan3() {
    __shared__ int sb[64];
    __shared__ int base;
    int t = threadIdx.x;
    if (t < 64) sb[t] = (t < blockIdx.x) ? g_bsum[t] : 0;
    __syncthreads();
    if (t == 0) {
        int a = 0;
        #pragma unroll
        for (int b = 0; b < 64; b++) a += sb[b];
        base = a;
    }
    __syncthreads();
    int i = blockIdx.x * 1024 + t;
    if (i < N_NODES) {
        int o = g_off[i] + base;
        g_off[i] = o;
        g_cur[i] = o;
    }
    if (i == 0) g_off[N_NODES] = N_EDGES;
}

__global__ void k_fill(const int* __restrict__ ei) {
    int e = blockIdx.x * blockDim.x + threadIdx.x;
    if (e < N_EDGES) {
        int s = clampN(ei[e]);
        int d = clampN(ei[N_EDGES + e]);
        int p = atomicAdd(&g_cur[d], 1);
        if (p >= 0 && p < N_EDGES) g_esrc[p] = s;
    }
}

// ---------------- mean aggregation: one warp per node (FIN = 96) ------------
template <int SRC>
__global__ void k_agg(const float* __restrict__ ext) {
    const float* hin = src_ptr(SRC, ext);
    int w    = (blockIdx.x * blockDim.x + threadIdx.x) >> 5;
    int lane = threadIdx.x & 31;
    if (w >= N_NODES) return;
    int beg = g_off[w], end = g_off[w + 1];
    float a0 = 0.f, a1 = 0.f, a2 = 0.f;
    int e = beg;
    for (; e + 3 < end; e += 4) {
        const float* r0 = hin + (size_t)g_esrc[e]     * FIN;
        const float* r1 = hin + (size_t)g_esrc[e + 1] * FIN;
        const float* r2 = hin + (size_t)g_esrc[e + 2] * FIN;
        const float* r3 = hin + (size_t)g_esrc[e + 3] * FIN;
        float x0 = r0[lane], x1 = r0[lane + 32], x2 = r0[lane + 64];
        float y0 = r1[lane], y1 = r1[lane + 32], y2 = r1[lane + 64];
        float z0 = r2[lane], z1 = r2[lane + 32], z2 = r2[lane + 64];
        float u0 = r3[lane], u1 = r3[lane + 32], u2 = r3[lane + 64];
        a0 += (x0 + y0) + (z0 + u0);
        a1 += (x1 + y1) + (z1 + u1);
        a2 += (x2 + y2) + (z2 + u2);
    }
    for (; e < end; e++) {
        const float* r0 = hin + (size_t)g_esrc[e] * FIN;
        a0 += r0[lane]; a1 += r0[lane + 32]; a2 += r0[lane + 64];
    }
    int deg = end - beg;
    float inv = 1.0f / (float)(deg > 0 ? deg : 1);
    float* o = g_mean + (size_t)w * FIN;
    o[lane] = a0 * inv; o[lane + 32] = a1 * inv; o[lane + 64] = a2 * inv;
}

// ---------------- fused dual-GEMM + bias + ReLU (FFMA2) ----------------------
// out[i][j] = relu( sum_k mean[i][k]*Wl[k][j] + hin[i][k]*Wr[k][j] + b[j] )
// Thread tile: 4 nodes x 12 cols (6 f32x2 pairs).
template <int FOUT, int SRC, int DST>
__global__ void __launch_bounds__(128) k_gemm(
    const float* __restrict__ ext_in,
    const float* __restrict__ Wl, const float* __restrict__ Wr,
    const float* __restrict__ bias, float* __restrict__ ext_out)
{
    const float* hin = src_ptr(SRC, ext_in);
    float* out = dst_ptr(DST, ext_out);

    constexpr int JT = FOUT / 12;   // 8 (FOUT=96) or 4 (FOUT=48)
    constexpr int NG = 128 / JT;    // 16 or 32 node groups
    constexpr int TN = NG * 4;      // 64 or 128 nodes per block
    constexpr int KC = 32;

    __shared__ float sWl[KC][FOUT];
    __shared__ float sWr[KC][FOUT];
    __shared__ float sM[TN][KC + 1];
    __shared__ float sH[TN][KC + 1];

    int tid = threadIdx.x;
    int jg  = tid % JT;
    int ig  = tid / JT;
    int j0  = jg * 12;
    int node0 = blockIdx.x * TN;

    ull acc[4][6];
    #pragma unroll
    for (int r = 0; r < 4; r++)
        #pragma unroll
        for (int p = 0; p < 6; p++) acc[r][p] = 0ull;

    for (int kc = 0; kc < FIN; kc += KC) {
        __syncthreads();
        // weights: float4 global loads, float4 smem stores
        #pragma unroll
        for (int idx = tid; idx < KC * FOUT / 4; idx += 128) {
            int kk = idx / (FOUT / 4), j4 = idx % (FOUT / 4);
            float4 vl = *(const float4*)&Wl[(kc + kk) * FOUT + j4 * 4];
            float4 vr = *(const float4*)&Wr[(kc + kk) * FOUT + j4 * 4];
            *(float4*)&sWl[kk][j4 * 4] = vl;
            *(float4*)&sWr[kk][j4 * 4] = vr;
        }
        // node features: float4 global loads, scalar smem stores (padded rows)
        #pragma unroll
        for (int idx = tid; idx < TN * (KC / 4); idx += 128) {
            int ii = idx / (KC / 4), q = idx % (KC / 4);
            int row = node0 + ii; row = row < N_NODES ? row : N_NODES - 1;
            size_t base = (size_t)row * FIN + kc + q * 4;
            float4 m = *(const float4*)&g_mean[base];
            float4 h = *(const float4*)&hin[base];
            sM[ii][q*4+0]=m.x; sM[ii][q*4+1]=m.y; sM[ii][q*4+2]=m.z; sM[ii][q*4+3]=m.w;
            sH[ii][q*4+0]=h.x; sH[ii][q*4+1]=h.y; sH[ii][q*4+2]=h.z; sH[ii][q*4+3]=h.w;
        }
        __syncthreads();

        #pragma unroll 2
        for (int k = 0; k < KC; k++) {
            ull wl[6], wr[6];
            #pragma unroll
            for (int p = 0; p < 6; p++) {
                float2 l = *(const float2*)&sWl[k][j0 + 2 * p];
                float2 r = *(const float2*)&sWr[k][j0 + 2 * p];
                wl[p] = pack2(l.x, l.y);
                wr[p] = pack2(r.x, r.y);
            }
            #pragma unroll
            for (int r = 0; r < 4; r++) {
                int ii = ig * 4 + r;
                float mv = sM[ii][k];
                float hv = sH[ii][k];
                ull m2 = pack2(mv, mv);
                ull h2 = pack2(hv, hv);
                #pragma unroll
                for (int p = 0; p < 6; p++)
                    acc[r][p] = fma2(m2, wl[p], fma2(h2, wr[p], acc[r][p]));
            }
        }
    }

    // epilogue: bias + relu, float2 stores
    float2 bj[6];
    #pragma unroll
    for (int p = 0; p < 6; p++) bj[p] = *(const float2*)&bias[j0 + 2 * p];

    #pragma unroll
    for (int r = 0; r < 4; r++) {
        int node = node0 + ig * 4 + r;
        if (node < N_NODES) {
            float* o = out + (size_t)node * FOUT + j0;
            #pragma unroll
            for (int p = 0; p < 6; p++) {
                float2 v = unpack2(acc[r][p]);
                float2 s;
                s.x = fmaxf(v.x + bj[p].x, 0.f);
                s.y = fmaxf(v.y + bj[p].y, 0.f);
                *(float2*)&o[2 * p] = s;
            }
        }
    }
}

// ---------------- launch ------------------------------------------------------
extern "C" void kernel_launch(void* const* d_in, const int* in_sizes, int n_in,
                              void* d_out, int out_size)
{
    const float* x   = (const float*)d_in[0];
    const int*   ei  = (const int*)d_in[1];     // int32 (JAX x64 disabled)
    const float* Wl0 = (const float*)d_in[2];
    const float* Wr0 = (const float*)d_in[3];
    const float* b0  = (const float*)d_in[4];
    const float* Wl1 = (const float*)d_in[5];
    const float* Wr1 = (const float*)d_in[6];
    const float* b1  = (const float*)d_in[7];
    const float* Wl2 = (const float*)d_in[8];
    const float* Wr2 = (const float*)d_in[9];
    const float* b2  = (const float*)d_in[10];
    float*       out = (float*)d_out;

    const int nScanBlk = (N_NODES + 1023) / 1024;   // 49
    const int nEdgeBlk = (N_EDGES + 255) / 256;     // 3125

    // CSR build (5 launches)
    k_zero_deg<<<(N_NODES + 255) / 256, 256>>>();
    k_count<<<nEdgeBlk, 256>>>(ei);
    k_scan1<<<nScanBlk, 1024>>>();
    k_scan3<<<nScanBlk, 1024>>>();
    k_fill<<<nEdgeBlk, 256>>>(ei);

    const int aggBlk = (N_NODES + 7) / 8;   // warp per node, 8 warps/block

    // layer 0: x -> g_h1       (GEMM: TN=64 -> 782 blocks)
    k_agg<0><<<aggBlk, 256>>>(x);
    k_gemm<96, 0, 1><<<(N_NODES + 63) / 64, 128>>>(x, Wl0, Wr0, b0, nullptr);
    // layer 1: g_h1 -> g_h2
    k_agg<1><<<aggBlk, 256>>>(nullptr);
    k_gemm<96, 1, 2><<<(N_NODES + 63) / 64, 128>>>(nullptr, Wl1, Wr1, b1, nullptr);
    // layer 2: g_h2 -> out     (FOUT=48: TN=128 -> 391 blocks)
    k_agg<2><<<aggBlk, 256>>>(nullptr);
    k_gemm<48, 2, 0><<<(N_NODES + 127) / 128, 128>>>(nullptr, Wl2, Wr2, b2, out);
}